// round 6
// baseline (speedup 1.0000x reference)
#include <cuda_runtime.h>
#include <cuda_bf16.h>

// B=32, C=512, H=W=64
//   d=max_HW x, e=mean_HW x ; y=softmax_j(d_i d_j + e_i e_j)
//   f_j = alpha*sum_i d_i y_ij + beta*sum_i e_i y_ij ; out[b,c,:,:]=f[b,c]
//
// SINGLE persistent kernel, 888 co-resident blocks (148 SMs x 6), grid barriers:
//   A: zero g_s/g_f + pool (block-per-tile, grid-strided, read 268MB)
//   -> bar0 -> B1: rowsum halves (128 blocks, 2-way atomicAdd, deterministic)
//   -> bar1 -> B2: colsum halves -> f (128 blocks, 2-way atomicAdd)
//   -> bar2 -> C: broadcast (warp-per-2KB-chunk, pipelined, write 268MB)
// Residency: launch_bounds(256,6) caps regs at 40; smem ~4.5KB/block ->
// 6 blocks/SM fits easily; 888/6 = 148 SMs -> all co-resident, no deadlock.
// No max-subtract: |logit| <= d_max^2 ~ 18 << 88 (exp finite in fp32).
// 2-contributor atomicAdd is deterministic: a+b == b+a bitwise in fp32.

#define BATCH 32
#define CH    512
#define HW    4096
#define BC    (BATCH * CH)
#define NB    888
#define NT    256
#define NWARP (NB * (NT / 32))    // 7104
#define NCHUNK (BC * 8)           // 2KB chunks of output

__device__ float    g_d[BC];
__device__ float    g_e[BC];
__device__ float    g_s[BC];      // softmax row sums (atomic-accumulated)
__device__ float    g_f[BC];      // final per-(b,c) value (atomic-accumulated)
__device__ unsigned g_ctr[3];
__device__ unsigned g_rel[3];     // monotonic generation counters

__device__ __forceinline__ unsigned ld_vol(const unsigned* p) {
    return *(volatile const unsigned*)p;
}

// Grid barrier, replay-safe: base = g_rel[k] snapshot taken at block start.
__device__ __forceinline__ void gbar(int k, unsigned base) {
    __syncthreads();
    if (threadIdx.x == 0) {
        __threadfence();
        if (atomicAdd(&g_ctr[k], 1u) == NB - 1u) {
            g_ctr[k] = 0;
            __threadfence();
            atomicAdd(&g_rel[k], 1u);
        }
        while (ld_vol(&g_rel[k]) == base) __nanosleep(128);
        __threadfence();
    }
    __syncthreads();
}

struct SmemT {
    union {
        float2 de[256];    // B1: (d_j, e_j) for j-half
        float4 pk[256];    // B2: (d_i, e_i, al*d_i/s_i, be*e_i/s_i) for i-half
    };
    float redmx[8];
    float redsm[8];
};

__global__ void __launch_bounds__(NT, 6)
fused_kernel(const float4* __restrict__ x, float4* __restrict__ out,
             const float* __restrict__ alpha, const float* __restrict__ beta) {
    __shared__ SmemT s;
    const int t   = threadIdx.x;
    const int blk = blockIdx.x;
    const int w   = t >> 5;
    const int ln  = t & 31;
    const int gw  = blk * (NT / 32) + w;

    unsigned b0 = 0, b1 = 0, b2 = 0;
    if (t == 0) { b0 = ld_vol(&g_rel[0]); b1 = ld_vol(&g_rel[1]); b2 = ld_vol(&g_rel[2]); }

    // ------- Phase A: zero accumulators + pool (block-per-tile, strided). ---
    if (blk < 64) {
        g_s[blk * NT + t] = 0.0f;
        g_f[blk * NT + t] = 0.0f;
    }
    for (int tile = blk; tile < BC; tile += NB) {
        const float4* p = x + (size_t)tile * (HW / 4);
        float4 v0 = __ldcs(p + t);
        float4 v1 = __ldcs(p + t + 256);
        float4 v2 = __ldcs(p + t + 512);
        float4 v3 = __ldcs(p + t + 768);
        float mxa = fmaxf(fmaxf(v0.x, v0.y), fmaxf(v0.z, v0.w));
        float mxb = fmaxf(fmaxf(v1.x, v1.y), fmaxf(v1.z, v1.w));
        mxa = fmaxf(mxa, fmaxf(fmaxf(v2.x, v2.y), fmaxf(v2.z, v2.w)));
        mxb = fmaxf(mxb, fmaxf(fmaxf(v3.x, v3.y), fmaxf(v3.z, v3.w)));
        float sma = ((v0.x + v0.y) + (v0.z + v0.w)) + ((v2.x + v2.y) + (v2.z + v2.w));
        float smb = ((v1.x + v1.y) + (v1.z + v1.w)) + ((v3.x + v3.y) + (v3.z + v3.w));
        float mx = fmaxf(mxa, mxb);
        float sm = sma + smb;
#pragma unroll
        for (int o = 16; o > 0; o >>= 1) {
            mx = fmaxf(mx, __shfl_xor_sync(0xFFFFFFFFu, mx, o));
            sm += __shfl_xor_sync(0xFFFFFFFFu, sm, o);
        }
        if (ln == 0) { s.redmx[w] = mx; s.redsm[w] = sm; }
        __syncthreads();
        if (t < 8) {
            mx = s.redmx[t];
            sm = s.redsm[t];
#pragma unroll
            for (int o = 4; o > 0; o >>= 1) {
                mx = fmaxf(mx, __shfl_xor_sync(0x000000FFu, mx, o));
                sm += __shfl_xor_sync(0x000000FFu, sm, o);
            }
            if (t == 0) {
                g_d[tile] = mx;
                g_e[tile] = sm * (1.0f / HW);
            }
        }
        __syncthreads();
    }
    gbar(0, b0);

    // ------- Phase B1: row-sum halves. 128 blocks = (b, i-half, j-half). ----
    if (blk < 128) {
        const int b  = blk >> 2;
        const int ih = (blk >> 1) & 1;
        const int jh = blk & 1;
        s.de[t] = make_float2(__ldcg(&g_d[b * CH + jh * 256 + t]),
                              __ldcg(&g_e[b * CH + jh * 256 + t]));
        __syncthreads();
        const int i  = ih * 256 + t;
        const float di = __ldcg(&g_d[b * CH + i]);
        const float ei = __ldcg(&g_e[b * CH + i]);
        float ssum = 0.0f;
#pragma unroll 8
        for (int j = 0; j < 256; ++j) {
            float2 v = s.de[j];
            ssum += __expf(fmaf(di, v.x, ei * v.y));
        }
        atomicAdd(&g_s[b * CH + i], ssum);   // 2 contributors -> deterministic
    }
    gbar(1, b1);

    // ------- Phase B2: col-sum halves -> f. 128 blocks = (b, ih, jh). -------
    if (blk < 128) {
        const int b  = blk >> 2;
        const int ih = (blk >> 1) & 1;
        const int jh = blk & 1;
        const float al = __ldg(alpha);
        const float be = __ldg(beta);
        {
            const int idx = b * CH + ih * 256 + t;
            const float d  = __ldcg(&g_d[idx]);
            const float e  = __ldcg(&g_e[idx]);
            const float inv = 1.0f / __ldcg(&g_s[idx]);
            s.pk[t] = make_float4(d, e, al * d * inv, be * e * inv);
        }
        __syncthreads();
        const int j  = jh * 256 + t;
        const float dj = __ldcg(&g_d[b * CH + j]);
        const float ej = __ldcg(&g_e[b * CH + j]);
        float fm = 0.0f, fe = 0.0f;
#pragma unroll 8
        for (int i = 0; i < 256; ++i) {
            float4 v = s.pk[i];
            float E = __expf(fmaf(dj, v.x, ej * v.y));
            fm = fmaf(v.z, E, fm);
            fe = fmaf(v.w, E, fe);
        }
        atomicAdd(&g_f[b * CH + j], fm + fe); // 2 contributors -> deterministic
    }
    gbar(2, b2);

    // ------- Phase C: broadcast, warp-per-2KB-chunk, pipelined f loads. -----
    {
        int c = gw;
        float fcur = (c < NCHUNK) ? __ldcg(&g_f[c >> 3]) : 0.0f;
        while (c < NCHUNK) {
            const int cn = c + NWARP;
            float fnext = 0.0f;
            if (cn < NCHUNK) fnext = __ldcg(&g_f[cn >> 3]);
            const float4 vv = make_float4(fcur, fcur, fcur, fcur);
            float4* p = out + ((size_t)c << 7) + ln;
            __stcs(p,      vv);
            __stcs(p + 32, vv);
            __stcs(p + 64, vv);
            __stcs(p + 96, vv);
            c = cn;
            fcur = fnext;
        }
    }
}

extern "C" void kernel_launch(void* const* d_in, const int* in_sizes, int n_in,
                              void* d_out, int out_size) {
    const float* x     = (const float*)d_in[0];
    const float* alpha = (const float*)d_in[1];
    const float* beta  = (const float*)d_in[2];
    float* out = (float*)d_out;

    fused_kernel<<<NB, NT>>>((const float4*)x, (float4*)out, alpha, beta);
}